// round 2
// baseline (speedup 1.0000x reference)
#include <cuda_runtime.h>
#include <cuda_bf16.h>
#include <cstdint>

#define N_NODES 100000
#define N_EDGES 1600000
#define DIM 128

// ---------------- scratch (static device memory; no runtime allocation) ----------------
__device__ float  g_deg[N_NODES];
__device__ float  g_norm[N_NODES];
__device__ float4 g_agg4[N_NODES * (DIM / 4)];   // 51.2 MB, 16B-aligned for red.v4

// ---------------- kernel 1: zero scratch ----------------
__global__ void zero_kernel() {
    int i = blockIdx.x * blockDim.x + threadIdx.x;
    int stride = gridDim.x * blockDim.x;
    const float4 z = make_float4(0.f, 0.f, 0.f, 0.f);
    for (int j = i; j < N_NODES * (DIM / 4); j += stride) g_agg4[j] = z;
    for (int j = i; j < N_NODES; j += stride) g_deg[j] = 0.f;
}

// ---------------- kernel 2: in-degree histogram ----------------
__global__ void deg_kernel(const int* __restrict__ edst) {
    int e = blockIdx.x * blockDim.x + threadIdx.x;
    if (e < N_EDGES) atomicAdd(&g_deg[edst[e]], 1.0f);
}

// ---------------- kernel 3: norm = clip(deg,1)^-0.5 ----------------
__global__ void norm_kernel() {
    int i = blockIdx.x * blockDim.x + threadIdx.x;
    if (i < N_NODES) g_norm[i] = rsqrtf(fmaxf(g_deg[i], 1.0f));
}

// ---------------- kernel 4: edge scatter (SpMM): agg[dst] += h[src]*norm[src] ----------------
// One warp per edge; each lane handles one float4 (4 of the 128 features).
__global__ void scatter_kernel(const float* __restrict__ h,
                               const int* __restrict__ esrc,
                               const int* __restrict__ edst) {
    int gt = blockIdx.x * blockDim.x + threadIdx.x;
    int e = gt >> 5;
    int lane = gt & 31;
    if (e >= N_EDGES) return;
    int src = __ldg(esrc + e);
    int dst = __ldg(edst + e);
    float ns = g_norm[src];
    float4 v = ((const float4*)(h + (size_t)src * DIM))[lane];
    v.x *= ns; v.y *= ns; v.z *= ns; v.w *= ns;
    float4* p = &g_agg4[(size_t)dst * (DIM / 4) + lane];
    asm volatile("red.global.add.v4.f32 [%0], {%1, %2, %3, %4};"
                 :: "l"(p), "f"(v.x), "f"(v.y), "f"(v.z), "f"(v.w)
                 : "memory");
}

// ---------------- kernel 5: out = (agg * norm_dst) @ W^T + b ----------------
// Classic register-tiled fp32 GEMM: BM=64, BN=128(full), BK=8, TM=8, TN=4, 256 threads.
#define BM 64
#define BN 128
#define BK 8
#define TM 8
#define TN 4

__global__ __launch_bounds__(256) void gemm_kernel(const float* __restrict__ W,
                                                   const float* __restrict__ bias,
                                                   float* __restrict__ out) {
    __shared__ float As[BK][BM];
    __shared__ float Bs[BK][BN];

    int tid = threadIdx.x;
    int block_m = blockIdx.x * BM;
    int tm = tid >> 5;   // 0..7  (uniform within warp -> As reads broadcast)
    int tn = tid & 31;   // 0..31 (lane -> conflict-free float4 Bs reads)

    float acc[TM][TN];
#pragma unroll
    for (int i = 0; i < TM; i++)
#pragma unroll
        for (int j = 0; j < TN; j++) acc[i][j] = 0.f;

    const float* agg = (const float*)g_agg4;

    for (int k0 = 0; k0 < DIM; k0 += BK) {
        // ---- load A tile: 64 rows x 8 k (512 floats = 128 float4), threads 0..127
        if (tid < 128) {
            int m = tid >> 1;
            int koff = (tid & 1) * 4;
            int gm = block_m + m;
            float4 v = make_float4(0.f, 0.f, 0.f, 0.f);
            if (gm < N_NODES) {
                v = *(const float4*)(agg + (size_t)gm * DIM + k0 + koff);
                float nm = g_norm[gm];
                v.x *= nm; v.y *= nm; v.z *= nm; v.w *= nm;
            }
            As[koff + 0][m] = v.x;
            As[koff + 1][m] = v.y;
            As[koff + 2][m] = v.z;
            As[koff + 3][m] = v.w;
        }
        // ---- load B tile: Bs[k][j] = W[j][k0+k], 128 j x 8 k (1024 floats = 256 float4)
        {
            int j = tid >> 1;
            int koff = (tid & 1) * 4;
            float4 w = *(const float4*)(W + (size_t)j * DIM + k0 + koff);
            Bs[koff + 0][j] = w.x;
            Bs[koff + 1][j] = w.y;
            Bs[koff + 2][j] = w.z;
            Bs[koff + 3][j] = w.w;
        }
        __syncthreads();

#pragma unroll
        for (int k = 0; k < BK; k++) {
            float a[TM], bb[TN];
#pragma unroll
            for (int i = 0; i < TM; i++) a[i] = As[k][tm * TM + i];
#pragma unroll
            for (int j = 0; j < TN; j++) bb[j] = Bs[k][tn * TN + j];
#pragma unroll
            for (int i = 0; i < TM; i++)
#pragma unroll
                for (int j = 0; j < TN; j++) acc[i][j] += a[i] * bb[j];
        }
        __syncthreads();
    }

    // ---- epilogue: add bias, store
    float4 bv = *(const float4*)(bias + tn * TN);
#pragma unroll
    for (int i = 0; i < TM; i++) {
        int gm = block_m + tm * TM + i;
        if (gm < N_NODES) {
            float4 r;
            r.x = acc[i][0] + bv.x;
            r.y = acc[i][1] + bv.y;
            r.z = acc[i][2] + bv.z;
            r.w = acc[i][3] + bv.w;
            *(float4*)(out + (size_t)gm * DIM + tn * TN) = r;
        }
    }
}

// ---------------- launch ----------------
extern "C" void kernel_launch(void* const* d_in, const int* in_sizes, int n_in,
                              void* d_out, int out_size) {
    const float* h    = (const float*)d_in[0];
    const float* W    = (const float*)d_in[1];
    const float* bias = (const float*)d_in[2];
    const int* esrc   = (const int*)d_in[3];
    const int* edst   = (const int*)d_in[4];
    float* out = (float*)d_out;

    zero_kernel<<<2048, 256>>>();
    deg_kernel<<<(N_EDGES + 255) / 256, 256>>>(edst);
    norm_kernel<<<(N_NODES + 255) / 256, 256>>>();
    scatter_kernel<<<(N_EDGES * 32) / 256, 256>>>(h, esrc, edst);
    gemm_kernel<<<(N_NODES + BM - 1) / BM, 256>>>(W, bias, out);
}

// round 3
// speedup vs baseline: 1.6370x; 1.6370x over previous
#include <cuda_runtime.h>
#include <cuda_bf16.h>
#include <cstdint>

#define N_NODES 100000
#define N_EDGES 1600000
#define DIM 128

#define NODES_PER_SCAN_BLOCK 1024
#define N_SCAN_BLOCKS ((N_NODES + NODES_PER_SCAN_BLOCK - 1) / NODES_PER_SCAN_BLOCK)  // 98

// ---------------- static device scratch (no runtime allocation) ----------------
__device__ int   g_cnt[N_NODES];     // in-degree
__device__ int   g_cur[N_NODES];     // fill cursors
__device__ int   g_off[N_NODES];     // CSR row offsets (exclusive prefix of cnt)
__device__ int   g_csr[N_EDGES];     // CSR column (src) indices
__device__ float g_norm[N_NODES];
__device__ int   g_bsum[128];
__device__ int   g_boff[128];

// ---------------- kernel 1: zero counters ----------------
__global__ void zero_kernel() {
    int i = blockIdx.x * blockDim.x + threadIdx.x;
    int stride = gridDim.x * blockDim.x;
    for (int j = i; j < N_NODES; j += stride) { g_cnt[j] = 0; g_cur[j] = 0; }
}

// ---------------- kernel 2: in-degree histogram (int atomics) ----------------
__global__ void deg_kernel(const int* __restrict__ edst) {
    int e = blockIdx.x * blockDim.x + threadIdx.x;
    if (e < N_EDGES) atomicAdd(&g_cnt[edst[e]], 1);
}

// ---------------- kernel 3: norm = clip(deg,1)^-0.5 ----------------
__global__ void norm_kernel() {
    int i = blockIdx.x * blockDim.x + threadIdx.x;
    if (i < N_NODES) g_norm[i] = rsqrtf(fmaxf((float)g_cnt[i], 1.0f));
}

// ---------------- scan pass 1: per-block sums of 1024 counts ----------------
__global__ __launch_bounds__(256) void scan1_kernel() {
    int b = blockIdx.x, t = threadIdx.x;
    int base = b * NODES_PER_SCAN_BLOCK + t * 4;
    int s = 0;
#pragma unroll
    for (int q = 0; q < 4; q++) {
        int n = base + q;
        if (n < N_NODES) s += g_cnt[n];
    }
#pragma unroll
    for (int o = 16; o > 0; o >>= 1) s += __shfl_down_sync(0xffffffffu, s, o);
    __shared__ int ws[8];
    if ((t & 31) == 0) ws[t >> 5] = s;
    __syncthreads();
    if (t == 0) {
        int tot = 0;
#pragma unroll
        for (int i = 0; i < 8; i++) tot += ws[i];
        g_bsum[b] = tot;
    }
}

// ---------------- scan pass 2: exclusive scan of block sums (1 block) ----------------
__global__ __launch_bounds__(128) void scan2_kernel() {
    int t = threadIdx.x;
    int lane = t & 31, wid = t >> 5;
    int v = (t < N_SCAN_BLOCKS) ? g_bsum[t] : 0;
    int x = v;
#pragma unroll
    for (int o = 1; o < 32; o <<= 1) {
        int y = __shfl_up_sync(0xffffffffu, x, o);
        if (lane >= o) x += y;
    }
    __shared__ int wsum[4];
    if (lane == 31) wsum[wid] = x;
    __syncthreads();
    if (t == 0) {
        int r = 0;
#pragma unroll
        for (int i = 0; i < 4; i++) { int tmp = wsum[i]; wsum[i] = r; r += tmp; }
    }
    __syncthreads();
    int incl = x + wsum[wid];
    if (t < N_SCAN_BLOCKS) g_boff[t] = incl - v;   // exclusive
}

// ---------------- scan pass 3: per-node exclusive offsets ----------------
__global__ __launch_bounds__(256) void scan3_kernel() {
    int b = blockIdx.x, t = threadIdx.x;
    int lane = t & 31, wid = t >> 5;
    int base = b * NODES_PER_SCAN_BLOCK + t * 4;
    int c[4];
    int tsum = 0;
#pragma unroll
    for (int q = 0; q < 4; q++) {
        c[q] = (base + q < N_NODES) ? g_cnt[base + q] : 0;
        tsum += c[q];
    }
    int x = tsum;
#pragma unroll
    for (int o = 1; o < 32; o <<= 1) {
        int y = __shfl_up_sync(0xffffffffu, x, o);
        if (lane >= o) x += y;
    }
    __shared__ int wsum[8], woff[8];
    if (lane == 31) wsum[wid] = x;
    __syncthreads();
    if (t == 0) {
        int r = 0;
#pragma unroll
        for (int i = 0; i < 8; i++) { woff[i] = r; r += wsum[i]; }
    }
    __syncthreads();
    int run = (x - tsum) + woff[wid] + g_boff[b];
#pragma unroll
    for (int q = 0; q < 4; q++) {
        if (base + q < N_NODES) g_off[base + q] = run;
        run += c[q];
    }
}

// ---------------- CSR fill ----------------
__global__ void fill_kernel(const int* __restrict__ esrc, const int* __restrict__ edst) {
    int e = blockIdx.x * blockDim.x + threadIdx.x;
    if (e < N_EDGES) {
        int d = edst[e];
        int pos = atomicAdd(&g_cur[d], 1);
        g_csr[g_off[d] + pos] = esrc[e];
    }
}

// ---------------- fused aggregate + GEMM ----------------
// Block = 64 dst rows. Phase 1: warps pull-aggregate rows into smem (no atomics).
// Phase 2: register-tiled GEMM (TM=8, TN=4) against W, bias epilogue.
#define BM 64
#define A_PAD 132   // 64x132 floats; float4 stores stay 16B-aligned, conflict-free

__global__ __launch_bounds__(256) void fused_kernel(const float* __restrict__ h,
                                                    const float* __restrict__ W,
                                                    const float* __restrict__ bias,
                                                    float* __restrict__ out) {
    __shared__ float As[BM][A_PAD];
    __shared__ float Bs[8][128];

    int tid = threadIdx.x;
    int wid = tid >> 5;
    int lane = tid & 31;
    int block_m = blockIdx.x * BM;

    // ---- phase 1: aggregation. Warp w handles rows w, w+8, ..., w+56.
    for (int r = wid; r < BM; r += 8) {
        int gm = block_m + r;
        float4 acc = make_float4(0.f, 0.f, 0.f, 0.f);
        if (gm < N_NODES) {
            int beg = g_off[gm];
            int end = beg + g_cnt[gm];
            for (int j = beg; j < end; j++) {
                int src = g_csr[j];          // uniform per warp -> single request
                float ns = g_norm[src];
                float4 v = ((const float4*)(h + (size_t)src * DIM))[lane];
                acc.x += v.x * ns;
                acc.y += v.y * ns;
                acc.z += v.z * ns;
                acc.w += v.w * ns;
            }
            float nd = g_norm[gm];
            acc.x *= nd; acc.y *= nd; acc.z *= nd; acc.w *= nd;
        }
        *(float4*)&As[r][lane * 4] = acc;
    }
    __syncthreads();

    // ---- phase 2: GEMM out[64x128] = As @ W^T + b
    int tm = tid >> 5;   // 0..7 (uniform within warp -> As reads broadcast)
    int tn = tid & 31;   // 0..31 (float4 Bs reads conflict-free)

    float facc[8][4];
#pragma unroll
    for (int i = 0; i < 8; i++)
#pragma unroll
        for (int j = 0; j < 4; j++) facc[i][j] = 0.f;

    for (int k0 = 0; k0 < DIM; k0 += 8) {
        // load W tile: Bs[k][j] = W[j][k0+k]
        {
            int j = tid >> 1;
            int koff = (tid & 1) * 4;
            float4 w = *(const float4*)(W + (size_t)j * DIM + k0 + koff);
            Bs[koff + 0][j] = w.x;
            Bs[koff + 1][j] = w.y;
            Bs[koff + 2][j] = w.z;
            Bs[koff + 3][j] = w.w;
        }
        __syncthreads();

#pragma unroll
        for (int k = 0; k < 8; k++) {
            float4 b4 = *(const float4*)&Bs[k][tn * 4];
            float bb[4] = { b4.x, b4.y, b4.z, b4.w };
#pragma unroll
            for (int i = 0; i < 8; i++) {
                float a = As[tm * 8 + i][k0 + k];   // warp-uniform broadcast
#pragma unroll
                for (int j = 0; j < 4; j++) facc[i][j] += a * bb[j];
            }
        }
        __syncthreads();
    }

    // ---- epilogue
    float4 bv = *(const float4*)(bias + tn * 4);
#pragma unroll
    for (int i = 0; i < 8; i++) {
        int gm = block_m + tm * 8 + i;
        if (gm < N_NODES) {
            float4 r;
            r.x = facc[i][0] + bv.x;
            r.y = facc[i][1] + bv.y;
            r.z = facc[i][2] + bv.z;
            r.w = facc[i][3] + bv.w;
            *(float4*)(out + (size_t)gm * DIM + tn * 4) = r;
        }
    }
}

// ---------------- launch ----------------
extern "C" void kernel_launch(void* const* d_in, const int* in_sizes, int n_in,
                              void* d_out, int out_size) {
    const float* h    = (const float*)d_in[0];
    const float* W    = (const float*)d_in[1];
    const float* bias = (const float*)d_in[2];
    const int* esrc   = (const int*)d_in[3];
    const int* edst   = (const int*)d_in[4];
    float* out = (float*)d_out;

    zero_kernel<<<256, 256>>>();
    deg_kernel<<<(N_EDGES + 255) / 256, 256>>>(edst);
    norm_kernel<<<(N_NODES + 255) / 256, 256>>>();
    scan1_kernel<<<N_SCAN_BLOCKS, 256>>>();
    scan2_kernel<<<1, 128>>>();
    scan3_kernel<<<N_SCAN_BLOCKS, 256>>>();
    fill_kernel<<<(N_EDGES + 255) / 256, 256>>>(esrc, edst);
    fused_kernel<<<(N_NODES + BM - 1) / BM, 256>>>(h, W, bias, out);
}